// round 8
// baseline (speedup 1.0000x reference)
#include <cuda_runtime.h>
#include <cstdint>

// VolumeRenderer: per-ray exclusive-cumprod transmittance * alpha, dot with rgb.
// alpha: [R, 128, 1] f32, rgbs: [R, 128, 3] f32 -> out [R, 3] f32.
// One warp per ray; lane l handles samples [4l, 4l+4).
// All 4 LDG.128 (w/ L2::256B promotion) issued back-to-back BEFORE the scan,
// so the warp takes one merged memory stall instead of two. 128-thread CTAs
// for finer tail-wave balancing.

#define EPS 1e-10f

__device__ __forceinline__ float4 ldg256(const float4* p) {
    float4 v;
    asm("ld.global.nc.L2::256B.v4.f32 {%0,%1,%2,%3}, [%4];"
        : "=f"(v.x), "=f"(v.y), "=f"(v.z), "=f"(v.w)
        : "l"(p));
    return v;
}

__global__ __launch_bounds__(128) void volume_render_kernel(
    const float* __restrict__ alpha,
    const float* __restrict__ rgbs,
    float* __restrict__ out,
    int R)
{
    const int warp_id = (blockIdx.x * blockDim.x + threadIdx.x) >> 5;
    const int lane = threadIdx.x & 31;
    if (warp_id >= R) return;

    const size_t ray = (size_t)warp_id;

    // ---- front-batch ALL loads: 4 x LDG.128, one scoreboard wait ----
    const float4 a4 = ldg256(reinterpret_cast<const float4*>(alpha + ray * 128) + lane);
    const float4* rg = reinterpret_cast<const float4*>(rgbs + ray * 384) + lane * 3;
    const float4 r0 = ldg256(rg + 0);
    const float4 r1 = ldg256(rg + 1);
    const float4 r2 = ldg256(rg + 2);

    const float t0 = 1.0f - a4.x + EPS;
    const float t1 = 1.0f - a4.y + EPS;
    const float t2 = 1.0f - a4.z + EPS;
    const float t3 = 1.0f - a4.w + EPS;

    // inclusive warp scan (product) of per-lane 4-factor products
    float incl = (t0 * t1) * (t2 * t3);
    #pragma unroll
    for (int off = 1; off < 32; off <<= 1) {
        const float v = __shfl_up_sync(0xffffffffu, incl, off);
        if (lane >= off) incl *= v;
    }
    float excl = __shfl_up_sync(0xffffffffu, incl, 1);
    if (lane == 0) excl = 1.0f;

    // ---- weighted accumulation over this lane's 4 samples ----
    float acc0 = 0.0f, acc1 = 0.0f, acc2 = 0.0f;
    float tr = excl;

    float w = tr * a4.x;
    acc0 = fmaf(w, r0.x, acc0); acc1 = fmaf(w, r0.y, acc1); acc2 = fmaf(w, r0.z, acc2);
    tr *= t0;

    w = tr * a4.y;
    acc0 = fmaf(w, r0.w, acc0); acc1 = fmaf(w, r1.x, acc1); acc2 = fmaf(w, r1.y, acc2);
    tr *= t1;

    w = tr * a4.z;
    acc0 = fmaf(w, r1.z, acc0); acc1 = fmaf(w, r1.w, acc1); acc2 = fmaf(w, r2.x, acc2);
    tr *= t2;

    w = tr * a4.w;
    acc0 = fmaf(w, r2.y, acc0); acc1 = fmaf(w, r2.z, acc1); acc2 = fmaf(w, r2.w, acc2);

    // ---- butterfly reduce the 3 channels across the warp ----
    #pragma unroll
    for (int off = 16; off > 0; off >>= 1) {
        acc0 += __shfl_xor_sync(0xffffffffu, acc0, off);
        acc1 += __shfl_xor_sync(0xffffffffu, acc1, off);
        acc2 += __shfl_xor_sync(0xffffffffu, acc2, off);
    }

    // lanes 0..2 write one channel each -> contiguous 12B store
    if (lane < 3) {
        const float v = (lane == 0) ? acc0 : ((lane == 1) ? acc1 : acc2);
        out[ray * 3 + lane] = v;
    }
}

extern "C" void kernel_launch(void* const* d_in, const int* in_sizes, int n_in,
                              void* d_out, int out_size)
{
    const float* alpha = (const float*)d_in[0];   // [R,128,1]
    const float* rgbs  = (const float*)d_in[1];   // [R,128,3]
    float* out = (float*)d_out;                   // [R,3]

    const int R = in_sizes[0] / 128;

    const int threads = 128;              // 4 warps/block = 4 rays/block
    const int rays_per_block = threads / 32;
    const int blocks = (R + rays_per_block - 1) / rays_per_block;

    volume_render_kernel<<<blocks, threads>>>(alpha, rgbs, out, R);
}